// round 4
// baseline (speedup 1.0000x reference)
#include <cuda_runtime.h>

#define BATCH 8
#define SEQ   2048
#define VDIM  64
#define CHUNK 32
#define NCHUNK (SEQ / CHUNK)    // 64
#define NBLK   (BATCH * NCHUNK) // 512

// Scratch (__device__ globals per allocation-free rule)
__device__ float g_csum[NBLK * VDIM];   // per-chunk channel sums of v_j (j>=1)
__device__ float g_v0[VDIM];            // wo_w @ wv_bos
__device__ float g_d0[BATCH];           // h[b,0,:] . qk_direction

// ---------------------------------------------------------------------------
// K1 (skeletal): chunk aggregates; d0 for k==0 blocks; v0 from block 0
// ---------------------------------------------------------------------------
__global__ __launch_bounds__(256) void k1(
    const float* __restrict__ h,
    const float* __restrict__ wv,
    const float* __restrict__ qk_dir,
    const float* __restrict__ wo_w,
    const float* __restrict__ wv_bos)
{
    __shared__ float part[4][VDIM];
    __shared__ float pre[4][VDIM];

    const int b   = blockIdx.x / NCHUNK;
    const int k   = blockIdx.x % NCHUNK;
    const int tid = threadIdx.x;
    const int g   = tid >> 6;    // 0..3, 8 rows each
    const int c   = tid & 63;

    const float* hb = h + (size_t)b * SEQ * VDIM;
    const float* rp = hb + (size_t)(k * CHUNK + g * 8) * VDIM + c;

    // 8 independent coalesced loads, summed (exclude global row 0)
    float s = 0.f;
    #pragma unroll
    for (int r = 0; r < 8; r++) {
        float x = rp[r * VDIM];
        if (!(k == 0 && g == 0 && r == 0)) s += x;
    }
    part[g][c] = s * wv[c];

    // d0 per batch (blocks with k==0, warp 0)
    if (k == 0 && tid < 32) {
        float pd = hb[tid] * qk_dir[tid] + hb[tid + 32] * qk_dir[tid + 32];
        #pragma unroll
        for (int o = 16; o > 0; o >>= 1) pd += __shfl_xor_sync(0xffffffffu, pd, o);
        if (tid == 0) g_d0[b] = pd;
    }

    // v0 = wo_w @ wv_bos (block 0 only)
    if (blockIdx.x == 0) {
        float p = 0.f;
        #pragma unroll
        for (int j = g * 16; j < g * 16 + 16; j++)
            p += wo_w[c * VDIM + j] * wv_bos[j];
        pre[g][c] = p;
    }
    __syncthreads();

    if (tid < VDIM)
        g_csum[blockIdx.x * VDIM + tid] =
            part[0][tid] + part[1][tid] + part[2][tid] + part[3][tid];
    if (blockIdx.x == 0 && tid < VDIM)
        g_v0[tid] = pre[0][tid] + pre[1][tid] + pre[2][tid] + pre[3][tid];
}

// ---------------------------------------------------------------------------
// K2: dots + weights + prefix + recurrence -> output
// ---------------------------------------------------------------------------
__global__ __launch_bounds__(256) void k2(
    const float* __restrict__ h,
    const float* __restrict__ wv,
    const float* __restrict__ qk_bos,
    const float* __restrict__ qk_prev,
    float* __restrict__ out)
{
    __shared__ float  hs[CHUNK * VDIM];   // raw h tile for dots (8 KB)
    __shared__ float  part[4][VDIM];
    __shared__ float  pre[4][VDIM];
    __shared__ float4 w4s[CHUNK];

    const int b    = blockIdx.x / NCHUNK;
    const int k    = blockIdx.x % NCHUNK;
    const int tid  = threadIdx.x;
    const int lane = tid & 31;
    const int w    = tid >> 5;
    const int g    = tid >> 6;
    const int c    = tid & 63;

    const float* hb = h + (size_t)b * SEQ * VDIM;
    const int i0    = k * CHUNK;
    const int rbase = g * 8;

    const float wvc = wv[c];
    const float d0  = g_d0[b];
    const float v0c = g_v0[c];

    // cross-chunk prefix partials (independent L2 loads — issue early)
    float p = 0.f;
    for (int j = g; j < k; j += 4)
        p += g_csum[(b * NCHUNK + j) * VDIM + c];

    // my group's 8 raw rows + predecessor row (L2 hits)
    float hr[8];
    {
        const float* rp = hb + (size_t)(i0 + rbase) * VDIM + c;
        #pragma unroll
        for (int r = 0; r < 8; r++) hr[r] = rp[r * VDIM];
    }
    float vm1 = 0.f;
    {
        const int ip = i0 + rbase - 1;
        if (ip >= 0) vm1 = hb[(size_t)ip * VDIM + c] * wvc;
    }

    // stage raw tile for the dot warps
    #pragma unroll
    for (int r = 0; r < 8; r++) hs[(rbase + r) * VDIM + c] = hr[r];

    // within-chunk group sum of v (exclude global row 0)
    {
        float gs = 0.f;
        #pragma unroll
        for (int r = 0; r < 8; r++) {
            if (k == 0 && g == 0 && r == 0) continue;
            gs += hr[r];
        }
        part[g][c] = gs * wvc;
    }
    pre[g][c] = p;
    __syncthreads();

    // dots + closed-form softmax weights: warp w -> rows 4w..4w+3
    {
        const float qbl = qk_bos[lane],  qbh = qk_bos[lane + 32];
        const float qpl = qk_prev[lane], qph = qk_prev[lane + 32];
        #pragma unroll
        for (int r = w * 4; r < w * 4 + 4; r++) {
            float hl = hs[r * VDIM + lane];
            float hh = hs[r * VDIM + lane + 32];
            float pa = hl * qbl + hh * qbh;
            float ps = hl * qpl + hh * qph;
            #pragma unroll
            for (int o = 16; o > 0; o >>= 1) {
                pa += __shfl_xor_sync(0xffffffffu, pa, o);
                ps += __shfl_xor_sync(0xffffffffu, ps, o);
            }
            const int i = i0 + r;
            const float a = pa * d0;   // column-0 logit
            const float s = ps;        // sub-diagonal logit
            float4 wt;
            if (i == 0) {
                wt = make_float4(1.f, 0.f, 0.f, 0.f);
            } else if (i == 1) {
                float t  = a + s;
                float m  = fmaxf(t, 0.f);
                float e  = __expf(t - m);
                float e1 = __expf(-m);
                float inv = 1.f / (e + e1);
                wt = make_float4(e * inv, 0.f, e1 * inv, 0.f);
            } else {
                float m  = fmaxf(fmaxf(a, s), 0.f);
                float ea = __expf(a - m);
                float es = __expf(s - m);
                float e0 = __expf(-m);
                float inv = 1.f / (ea + es + e0 * (float)(i - 1));
                wt = make_float4(ea * inv, es * inv, e0 * inv, 0.f);
            }
            if (lane == 0) w4s[r] = wt;
        }
    }

    // Sbefore (independent of the dot warps' output)
    float Sbefore = pre[0][c] + pre[1][c] + pre[2][c] + pre[3][c];
    #pragma unroll
    for (int gp = 0; gp < 3; gp++)
        if (gp < g) Sbefore += part[gp][c];
    __syncthreads();

    // 8-step recurrence
    float S2 = Sbefore - vm1;
    float* ob = out + (size_t)b * SEQ * VDIM;
    #pragma unroll
    for (int r = 0; r < 8; r++) {
        const int i = i0 + rbase + r;
        const float4 wt = w4s[rbase + r];
        const float vi = hr[r] * wvc;
        const float o = wt.x * v0c + wt.y * vm1 + wt.z * (S2 + vi);
        ob[(size_t)i * VDIM + c] = o;
        S2 += vm1;
        vm1 = vi;
        if (k == 0 && g == 0 && (rbase + r) < 2) S2 = 0.f;  // rows 0,1 special
    }
}

// ---------------------------------------------------------------------------
extern "C" void kernel_launch(void* const* d_in, const int* in_sizes, int n_in,
                              void* d_out, int out_size)
{
    const float* h        = (const float*)d_in[0];
    // d_in[1], d_in[2]: mask_one / mask_zero — causal structure hardcoded
    const float* wv_bos   = (const float*)d_in[3];
    const float* wv       = (const float*)d_in[4];
    const float* wo_w     = (const float*)d_in[5];
    const float* qk_dir   = (const float*)d_in[6];
    const float* qk_bos   = (const float*)d_in[7];
    const float* qk_prev  = (const float*)d_in[8];
    float* out = (float*)d_out;

    k1<<<NBLK, 256>>>(h, wv, qk_dir, wo_w, wv_bos);
    k2<<<NBLK, 256>>>(h, wv, qk_bos, qk_prev, out);
}

// round 5
// speedup vs baseline: 1.0278x; 1.0278x over previous
#include <cuda_runtime.h>

#define BATCH 8
#define SEQ   2048
#define VDIM  64
#define CHUNK 32
#define NCHUNK (SEQ / CHUNK)    // 64
#define NBLK   (BATCH * NCHUNK) // 512

// Scratch (__device__ globals per allocation-free rule)
__device__ float g_csum[NBLK * VDIM];    // per-chunk channel sums of v_j (j>=1)
__device__ float g_v0[BATCH * VDIM];     // wo_w @ wv_bos (published per batch)
__device__ int   g_cnt[BATCH];           // arrival counters (zeroed each launch)

__global__ __launch_bounds__(256, 4) void kF(
    const float* __restrict__ h,
    const float* __restrict__ wv,
    const float* __restrict__ wv_bos,
    const float* __restrict__ wo_w,
    const float* __restrict__ qk_dir,
    const float* __restrict__ qk_bos,
    const float* __restrict__ qk_prev,
    float* __restrict__ out)
{
    __shared__ float  hs[CHUNK * VDIM];   // raw h tile (8 KB), for the dot warps
    __shared__ float  part[4][VDIM];      // within-chunk group value sums
    __shared__ float  pre[4][VDIM];       // v0 partials, then prefix partials
    __shared__ float4 w4s[CHUNK];         // per-row softmax weights
    __shared__ float  sd0;

    const int b    = blockIdx.x / NCHUNK;
    const int k    = blockIdx.x % NCHUNK;
    const int tid  = threadIdx.x;
    const int lane = tid & 31;
    const int w    = tid >> 5;
    const int g    = tid >> 6;    // row-group 0..3 (8 rows each)
    const int c    = tid & 63;    // channel

    const float* hb = h + (size_t)b * SEQ * VDIM;
    const int i0    = k * CHUNK;
    const int rbase = g * 8;
    const float wvc = wv[c];

    // ---- phase 1: load my 8 rows (registers), stage tile, group sums ----
    float hr[8];
    {
        const float* rp = hb + (size_t)(i0 + rbase) * VDIM + c;
        #pragma unroll
        for (int r = 0; r < 8; r++) hr[r] = rp[r * VDIM];
    }
    float vm1 = 0.f;                       // previous-row value (g==0 path: global)
    if (g == 0 && k > 0)
        vm1 = hb[(size_t)(i0 - 1) * VDIM + c] * wvc;

    // d0 = h[b,0,:] . qk_dir (warp 0, redundant per block — L2 hit)
    if (w == 0) {
        float pd = hb[lane] * qk_dir[lane] + hb[lane + 32] * qk_dir[lane + 32];
        #pragma unroll
        for (int o = 16; o > 0; o >>= 1) pd += __shfl_xor_sync(0xffffffffu, pd, o);
        if (lane == 0) sd0 = pd;
    }

    #pragma unroll
    for (int r = 0; r < 8; r++) hs[(rbase + r) * VDIM + c] = hr[r];

    {
        float gs = 0.f;
        #pragma unroll
        for (int r = 0; r < 8; r++) {
            if (k == 0 && g == 0 && r == 0) continue;   // exclude global row 0
            gs += hr[r];
        }
        part[g][c] = gs * wvc;
    }

    // v0 partials (k==0 block of each batch)
    if (k == 0) {
        float p = 0.f;
        #pragma unroll
        for (int j = g * 16; j < g * 16 + 16; j++)
            p += wo_w[c * VDIM + j] * wv_bos[j];
        pre[g][c] = p;
    }
    __syncthreads();   // sync1

    // pull previous-row value from the staged tile (g>0 path)
    if (g > 0) vm1 = hs[(rbase - 1) * VDIM + c] * wvc;

    // ---- publish aggregate (+ v0) then fence ----
    if (tid < VDIM) {
        g_csum[blockIdx.x * VDIM + tid] =
            part[0][tid] + part[1][tid] + part[2][tid] + part[3][tid];
        if (k == 0)
            g_v0[b * VDIM + tid] =
                pre[0][tid] + pre[1][tid] + pre[2][tid] + pre[3][tid];
        __threadfence();
    }
    __syncthreads();   // sync2: all publishes + fences done
    if (tid == 0) atomicAdd(&g_cnt[b], 1);

    // ---- overlapped: dots + closed-form softmax weights ----
    {
        const float qbl = qk_bos[lane],  qbh = qk_bos[lane + 32];
        const float qpl = qk_prev[lane], qph = qk_prev[lane + 32];
        const float d0  = sd0;
        #pragma unroll
        for (int r = w * 4; r < w * 4 + 4; r++) {
            float hl = hs[r * VDIM + lane];
            float hh = hs[r * VDIM + lane + 32];
            float pa = hl * qbl + hh * qbh;
            float ps = hl * qpl + hh * qph;
            #pragma unroll
            for (int o = 16; o > 0; o >>= 1) {
                pa += __shfl_xor_sync(0xffffffffu, pa, o);
                ps += __shfl_xor_sync(0xffffffffu, ps, o);
            }
            const int i = i0 + r;
            const float a = pa * d0;   // column-0 logit
            const float s = ps;        // sub-diagonal logit
            float4 wt;
            if (i == 0) {
                wt = make_float4(1.f, 0.f, 0.f, 0.f);
            } else if (i == 1) {
                float t  = a + s;
                float m  = fmaxf(t, 0.f);
                float e  = __expf(t - m);
                float e1 = __expf(-m);
                float inv = 1.f / (e + e1);
                wt = make_float4(e * inv, 0.f, e1 * inv, 0.f);
            } else {
                float m  = fmaxf(fmaxf(a, s), 0.f);
                float ea = __expf(a - m);
                float es = __expf(s - m);
                float e0 = __expf(-m);
                float inv = 1.f / (ea + es + e0 * (float)(i - 1));
                wt = make_float4(ea * inv, es * inv, e0 * inv, 0.f);
            }
            if (lane == 0) w4s[r] = wt;
        }
    }

    // ---- wait for all aggregates of this batch (arrive-before-poll, safe) ----
    if (tid == 0 && k > 0) {
        volatile int* cp = &g_cnt[b];
        while (*cp < NCHUNK) __nanosleep(40);
        __threadfence();
    }
    __syncthreads();   // sync3: releases block; compiler barrier for csum reads

    const float v0c = g_v0[b * VDIM + c];

    // ---- cross-chunk prefix partials (<=16 independent L2 loads) ----
    {
        float p = 0.f;
        for (int j = g; j < k; j += 4)
            p += g_csum[(b * NCHUNK + j) * VDIM + c];
        pre[g][c] = p;
    }
    __syncthreads();   // sync4

    float Sbefore = pre[0][c] + pre[1][c] + pre[2][c] + pre[3][c];
    #pragma unroll
    for (int gp = 0; gp < 3; gp++)
        if (gp < g) Sbefore += part[gp][c];

    // ---- 8-step recurrence ----
    float S2 = Sbefore - vm1;
    float* ob = out + (size_t)b * SEQ * VDIM;
    #pragma unroll
    for (int r = 0; r < 8; r++) {
        const int i = i0 + rbase + r;
        const float4 wt = w4s[rbase + r];
        const float vi = hr[r] * wvc;
        const float o = wt.x * v0c + wt.y * vm1 + wt.z * (S2 + vi);
        ob[(size_t)i * VDIM + c] = o;
        S2 += vm1;
        vm1 = vi;
        if (k == 0 && g == 0 && (rbase + r) < 2) S2 = 0.f;  // rows 0,1 special
    }
}

// ---------------------------------------------------------------------------
extern "C" void kernel_launch(void* const* d_in, const int* in_sizes, int n_in,
                              void* d_out, int out_size)
{
    const float* h        = (const float*)d_in[0];
    // d_in[1], d_in[2]: mask_one / mask_zero — causal structure hardcoded
    const float* wv_bos   = (const float*)d_in[3];
    const float* wv       = (const float*)d_in[4];
    const float* wo_w     = (const float*)d_in[5];
    const float* qk_dir   = (const float*)d_in[6];
    const float* qk_bos   = (const float*)d_in[7];
    const float* qk_prev  = (const float*)d_in[8];
    float* out = (float*)d_out;

    void* cnt_ptr = nullptr;
    cudaGetSymbolAddress(&cnt_ptr, g_cnt);
    cudaMemsetAsync(cnt_ptr, 0, sizeof(int) * BATCH);

    kF<<<NBLK, 256>>>(h, wv, wv_bos, wo_w, qk_dir, qk_bos, qk_prev, out);
}

// round 6
// speedup vs baseline: 1.0798x; 1.0505x over previous
#include <cuda_runtime.h>

#define BATCH 8
#define SEQ   2048
#define VDIM  64
#define CHUNK 128
#define NCHUNK (SEQ / CHUNK)    // 16
#define NBLK   (BATCH * NCHUNK) // 128
#define RPG    (CHUNK / 4)      // 32 rows per thread-group

// Scratch (__device__ globals per allocation-free rule)
__device__ float g_csum[NBLK * VDIM];   // per-chunk channel sums of v_j (j>=1)
__device__ int   g_cnt[BATCH];          // arrival counters (zeroed each launch)

__global__ __launch_bounds__(256) void kF(
    const float* __restrict__ h,
    const float* __restrict__ wv,
    const float* __restrict__ wv_bos,
    const float* __restrict__ wo_w,
    const float* __restrict__ qk_dir,
    const float* __restrict__ qk_bos,
    const float* __restrict__ qk_prev,
    float* __restrict__ out)
{
    __shared__ float  hs[CHUNK * VDIM];   // raw h tile (32 KB)
    __shared__ float  qbs[VDIM], qps[VDIM];
    __shared__ float  part[4][VDIM];      // group (32-row) value sums
    __shared__ float  pre[4][VDIM];       // v0 partials, later prefix partials
    __shared__ float4 w4s[CHUNK];         // per-row softmax weights
    __shared__ float  dpa[CHUNK][2], dps[CHUNK][2];
    __shared__ float  sd0;

    const int b    = blockIdx.x / NCHUNK;
    const int k    = blockIdx.x % NCHUNK;
    const int tid  = threadIdx.x;
    const int g    = tid >> 6;    // 0..3: rows g*32..g*32+31
    const int c    = tid & 63;    // channel

    const float* hb = h + (size_t)b * SEQ * VDIM;
    const int i0    = k * CHUNK;
    const int rbase = g * RPG;
    const float wvc = wv[c];

    // ---- phase 1: stream 32 rows -> smem, accumulate group sum ----
    {
        const float* rp = hb + (size_t)(i0 + rbase) * VDIM + c;
        float gs = 0.f;
        #pragma unroll
        for (int r = 0; r < RPG; r++) {
            float x = rp[(size_t)r * VDIM];
            hs[(rbase + r) * VDIM + c] = x;
            if (!(k == 0 && g == 0 && r == 0)) gs += x;   // exclude global row 0
        }
        part[g][c] = gs * wvc;
    }

    // stage q vectors
    if (tid < VDIM) { qbs[tid] = qk_bos[tid]; qps[tid] = qk_prev[tid]; }

    // d0 = h[b,0,:] . qk_dir (warp 0)
    if (tid < 32) {
        float pd = hb[tid] * qk_dir[tid] + hb[tid + 32] * qk_dir[tid + 32];
        #pragma unroll
        for (int o = 16; o > 0; o >>= 1) pd += __shfl_xor_sync(0xffffffffu, pd, o);
        if (tid == 0) sd0 = pd;
    }

    // v0 partials (every block, locally — no global round-trip)
    {
        float p = 0.f;
        #pragma unroll
        for (int j = g * 16; j < g * 16 + 16; j++)
            p += wo_w[c * VDIM + j] * wv_bos[j];
        pre[g][c] = p;
    }
    float vm1 = 0.f;
    if (g == 0 && k > 0) vm1 = hb[(size_t)(i0 - 1) * VDIM + c] * wvc;
    __syncthreads();   // sync1

    const float v0c = pre[0][c] + pre[1][c] + pre[2][c] + pre[3][c];
    if (g > 0) vm1 = hs[(rbase - 1) * VDIM + c] * wvc;

    // ---- publish chunk aggregate ----
    if (tid < VDIM) {
        g_csum[blockIdx.x * VDIM + tid] =
            part[0][tid] + part[1][tid] + part[2][tid] + part[3][tid];
        __threadfence();
    }
    __syncthreads();   // sync2
    if (tid == 0) atomicAdd(&g_cnt[b], 1);

    // ---- dots: 2 threads per row, staggered smem reads, no shfls ----
    {
        const int r    = tid & 127;
        const int half = tid >> 7;          // 0 or 1: channels half*32..+31
        float a0 = 0.f, a1 = 0.f, s0 = 0.f, s1 = 0.f;
        #pragma unroll
        for (int j0 = 0; j0 < 32; j0 += 2) {
            int ja = half * 32 + ((j0 + tid) & 31);
            int jb = half * 32 + ((j0 + 1 + tid) & 31);
            float ha = hs[r * VDIM + ja];
            float hb2 = hs[r * VDIM + jb];
            a0 += ha * qbs[ja];  s0 += ha * qps[ja];
            a1 += hb2 * qbs[jb]; s1 += hb2 * qps[jb];
        }
        dpa[r][half] = a0 + a1;
        dps[r][half] = s0 + s1;
    }
    __syncthreads();   // sync3

    // poll (thread 255 — idle during weight computation below)
    if (tid == 255 && k > 0) {
        volatile int* cp = &g_cnt[b];
        while (*cp < NCHUNK) __nanosleep(32);
        __threadfence();
    }

    // weights: one thread per row (tid < 128)
    if (tid < CHUNK) {
        const int r = tid;
        const int i = i0 + r;
        const float a = (dpa[r][0] + dpa[r][1]) * sd0;   // column-0 logit
        const float s = dps[r][0] + dps[r][1];           // sub-diagonal logit
        float4 wt;
        if (i == 0) {
            wt = make_float4(1.f, 0.f, 0.f, 0.f);
        } else if (i == 1) {
            float t  = a + s;
            float m  = fmaxf(t, 0.f);
            float e  = __expf(t - m);
            float e1 = __expf(-m);
            float inv = 1.f / (e + e1);
            wt = make_float4(e * inv, 0.f, e1 * inv, 0.f);
        } else {
            float m  = fmaxf(fmaxf(a, s), 0.f);
            float ea = __expf(a - m);
            float es = __expf(s - m);
            float e0 = __expf(-m);
            float inv = 1.f / (ea + es + e0 * (float)(i - 1));
            wt = make_float4(ea * inv, es * inv, e0 * inv, 0.f);
        }
        w4s[r] = wt;
    }
    __syncthreads();   // sync4: weights ready AND poll passed

    // ---- cross-chunk prefix partials (<=4 L2 loads per thread) ----
    {
        float p = 0.f;
        for (int j = g; j < k; j += 4)
            p += g_csum[(b * NCHUNK + j) * VDIM + c];
        pre[g][c] = p;
    }
    __syncthreads();   // sync5

    float Sbefore = pre[0][c] + pre[1][c] + pre[2][c] + pre[3][c];
    #pragma unroll
    for (int gp = 0; gp < 3; gp++)
        if (gp < g) Sbefore += part[gp][c];

    // ---- 32-step recurrence ----
    float S2 = Sbefore - vm1;
    float* ob = out + (size_t)b * SEQ * VDIM;
    #pragma unroll
    for (int r = 0; r < RPG; r++) {
        const int i = i0 + rbase + r;
        const float4 wt = w4s[rbase + r];
        const float vi = hs[(rbase + r) * VDIM + c] * wvc;
        const float o = wt.x * v0c + wt.y * vm1 + wt.z * (S2 + vi);
        ob[(size_t)i * VDIM + c] = o;
        S2 += vm1;
        vm1 = vi;
        if (k == 0 && g == 0 && (rbase + r) < 2) S2 = 0.f;  // rows 0,1 special
    }
}

// ---------------------------------------------------------------------------
extern "C" void kernel_launch(void* const* d_in, const int* in_sizes, int n_in,
                              void* d_out, int out_size)
{
    const float* h        = (const float*)d_in[0];
    // d_in[1], d_in[2]: mask_one / mask_zero — causal structure hardcoded
    const float* wv_bos   = (const float*)d_in[3];
    const float* wv       = (const float*)d_in[4];
    const float* wo_w     = (const float*)d_in[5];
    const float* qk_dir   = (const float*)d_in[6];
    const float* qk_bos   = (const float*)d_in[7];
    const float* qk_prev  = (const float*)d_in[8];
    float* out = (float*)d_out;

    void* cnt_ptr = nullptr;
    cudaGetSymbolAddress(&cnt_ptr, g_cnt);
    cudaMemsetAsync(cnt_ptr, 0, sizeof(int) * BATCH);

    kF<<<NBLK, 256>>>(h, wv, wv_bos, wo_w, qk_dir, qk_bos, qk_prev, out);
}